// round 2
// baseline (speedup 1.0000x reference)
#include <cuda_runtime.h>
#include <cuda_bf16.h>

// Problem constants
#define BATCH 512
#define SEQ   200
#define TT    10
#define EMB   25
#define HID   64
#define C3    192          // 3*HID
#define KV    92           // padded combined vec length: 25 x + 3 pad + 64 h
#define XOFF  28           // h part starts at row 28 of the combined matrix

// ---------------- scratch (device globals: no allocation allowed) ----------
__device__ float g_x[BATCH * SEQ * EMB];        // mean-pooled embeddings
__device__ float g_mask[BATCH * SEQ];           // step mask as float 0/1
__device__ float g_rnn[(size_t)BATCH * SEQ * 128]; // concat(hs_f, hs_b)
__device__ float g_hT[BATCH * HID];             // final forward hidden

// ---------------- helpers --------------------------------------------------
union F2U { float2 f; unsigned long long u; };

static __device__ __forceinline__ float2 ffma2f(float2 a, float2 b, float2 c) {
    F2U A, B, C, D; A.f = a; B.f = b; C.f = c;
    asm("fma.rn.f32x2 %0, %1, %2, %3;" : "=l"(D.u) : "l"(A.u), "l"(B.u), "l"(C.u));
    return D.f;
}

static __device__ __forceinline__ float sigm_f(float x) {
    return __fdividef(1.0f, 1.0f + __expf(-x));
}
static __device__ __forceinline__ float tanh_f(float x) {
    float e = __expf(2.0f * x);
    return 1.0f - __fdividef(2.0f, e + 1.0f);
}

// ---------------- K1: embedding mean + step mask ---------------------------
// one warp per (b, s)
__global__ __launch_bounds__(256) void embed_kernel(
    const int* __restrict__ inp, const float* __restrict__ emb)
{
    int wid = threadIdx.x >> 5, lane = threadIdx.x & 31;
    int g = blockIdx.x * 8 + wid;               // (b,s) index
    if (g >= BATCH * SEQ) return;
    int base = g * TT;

    int tk = 0;
    if (lane < TT) tk = inp[base + lane];
    unsigned bal = __ballot_sync(0xffffffffu, (lane < TT) && (tk != 0));
    int cnt = __popc(bal);

    float acc = 0.0f;
    #pragma unroll
    for (int t = 0; t < TT; ++t) {
        int tok = __shfl_sync(0xffffffffu, tk, t);
        if (tok != 0 && lane < EMB) acc += emb[tok * EMB + lane];
    }
    float denom = (float)(cnt > 0 ? cnt : 1);
    if (lane < EMB) g_x[g * EMB + lane] = acc / denom;
    int tok0 = __shfl_sync(0xffffffffu, tk, 0);
    if (lane == 0) g_mask[g] = (tok0 != 0) ? 1.0f : 0.0f;
}

// ---------------- K2: bidirectional GRU ------------------------------------
// 128 blocks x 128 threads. Block = one direction, 8 batch rows.
// Each warp owns 2 rows (R=2); lane l owns hidden pair (2l, 2l+1).
// Combined matrix M = [W(25); pad(3); U(64)] (92 x 192) in shared.
__global__ __launch_bounds__(128) void gru_kernel(
    const float* __restrict__ Wf, const float* __restrict__ Uf, const float* __restrict__ bf,
    const float* __restrict__ Wb, const float* __restrict__ Ub, const float* __restrict__ bb)
{
    extern __shared__ float sh[];
    float2* M2 = (float2*)sh;                   // [92][96] as float2
    float* vecsh = sh + KV * C3;                // [8][92]

    const int dir = blockIdx.x >> 6;            // 0 fwd, 1 bwd
    const int rowbase = (blockIdx.x & 63) * 8;
    const float* Wm = dir ? Wb : Wf;
    const float* Um = dir ? Ub : Uf;
    const float* bm = dir ? bb : bf;

    const int tid = threadIdx.x;
    for (int idx = tid; idx < KV * C3; idx += 128) {
        int r = idx / C3, c = idx - r * C3;
        float v = 0.0f;
        if (r < EMB)       v = Wm[r * C3 + c];
        else if (r >= XOFF) v = Um[(r - XOFF) * C3 + c];
        sh[idx] = v;
    }
    for (int idx = tid; idx < 8 * KV; idx += 128) vecsh[idx] = 0.0f;
    __syncthreads();

    const int wid = tid >> 5, lane = tid & 31;
    const int r0 = rowbase + wid * 2, r1 = r0 + 1;
    float* v0 = vecsh + (wid * 2) * KV;
    float* v1 = v0 + KV;
    const int c0 = 2 * lane;

    // gate biases (b0 = input bias, b1 = recurrent bias)
    float2 bz  = make_float2(bm[c0]       + bm[192 + c0],       bm[c0 + 1]       + bm[193 + c0]);
    float2 br  = make_float2(bm[64 + c0]  + bm[256 + c0],       bm[65 + c0]      + bm[257 + c0]);
    float2 bhx = make_float2(bm[128 + c0],                      bm[129 + c0]);
    float2 bhu = make_float2(bm[320 + c0],                      bm[321 + c0]);

    float2 h0 = make_float2(0.f, 0.f), h1 = make_float2(0.f, 0.f);

    // prefetch first step
    int s = dir ? (SEQ - 1) : 0;
    float xa = 0.f, xb = 0.f;
    if (lane < EMB) {
        xa = g_x[(r0 * SEQ + s) * EMB + lane];
        xb = g_x[(r1 * SEQ + s) * EMB + lane];
    }
    float m0 = g_mask[r0 * SEQ + s];
    float m1 = g_mask[r1 * SEQ + s];

    for (int t = 0; t < SEQ; ++t) {
        s = dir ? (SEQ - 1 - t) : t;
        if (lane < EMB) { v0[lane] = xa; v1[lane] = xb; }
        __syncwarp();   // x staged + previous step's h visible to all lanes

        // prefetch next step
        float xna = 0.f, xnb = 0.f, mn0 = 0.f, mn1 = 0.f;
        if (t < SEQ - 1) {
            int sn = dir ? (SEQ - 2 - t) : (t + 1);
            if (lane < EMB) {
                xna = g_x[(r0 * SEQ + sn) * EMB + lane];
                xnb = g_x[(r1 * SEQ + sn) * EMB + lane];
            }
            mn0 = g_mask[r0 * SEQ + sn];
            mn1 = g_mask[r1 * SEQ + sn];
        }

        float2 z0 = bz, z1 = bz, rg0 = br, rg1 = br;
        float2 hx0 = bhx, hx1 = bhx, hu0 = bhu, hu1 = bhu;

        // x part (rows 0..27, pad rows are zero)
        for (int k4 = 0; k4 < 7; ++k4) {
            float4 a4 = *(const float4*)(v0 + 4 * k4);
            float4 b4 = *(const float4*)(v1 + 4 * k4);
            const float2* row = M2 + (k4 * 4) * 96 + lane;
            float av[4] = {a4.x, a4.y, a4.z, a4.w};
            float bv[4] = {b4.x, b4.y, b4.z, b4.w};
            #pragma unroll
            for (int c = 0; c < 4; ++c) {
                float2 mz = row[0], mr = row[32], mh = row[64];
                row += 96;
                float2 va2 = make_float2(av[c], av[c]);
                float2 vb2 = make_float2(bv[c], bv[c]);
                z0  = ffma2f(va2, mz, z0);   z1  = ffma2f(vb2, mz, z1);
                rg0 = ffma2f(va2, mr, rg0);  rg1 = ffma2f(vb2, mr, rg1);
                hx0 = ffma2f(va2, mh, hx0);  hx1 = ffma2f(vb2, mh, hx1);
            }
        }
        // h part (rows 28..91)
        for (int k4 = 7; k4 < 23; ++k4) {
            float4 a4 = *(const float4*)(v0 + 4 * k4);
            float4 b4 = *(const float4*)(v1 + 4 * k4);
            const float2* row = M2 + (k4 * 4) * 96 + lane;
            float av[4] = {a4.x, a4.y, a4.z, a4.w};
            float bv[4] = {b4.x, b4.y, b4.z, b4.w};
            #pragma unroll
            for (int c = 0; c < 4; ++c) {
                float2 mz = row[0], mr = row[32], mh = row[64];
                row += 96;
                float2 va2 = make_float2(av[c], av[c]);
                float2 vb2 = make_float2(bv[c], bv[c]);
                z0  = ffma2f(va2, mz, z0);   z1  = ffma2f(vb2, mz, z1);
                rg0 = ffma2f(va2, mr, rg0);  rg1 = ffma2f(vb2, mr, rg1);
                hu0 = ffma2f(va2, mh, hu0);  hu1 = ffma2f(vb2, mh, hu1);
            }
        }

        // gates row0
        {
            float2 z, r, hh, hn;
            z.x = sigm_f(z0.x);  z.y = sigm_f(z0.y);
            r.x = sigm_f(rg0.x); r.y = sigm_f(rg0.y);
            hh.x = tanh_f(hx0.x + r.x * hu0.x);
            hh.y = tanh_f(hx0.y + r.y * hu0.y);
            hn.x = hh.x + z.x * (h0.x - hh.x);
            hn.y = hh.y + z.y * (h0.y - hh.y);
            hn.x = h0.x + m0 * (hn.x - h0.x);
            hn.y = h0.y + m0 * (hn.y - h0.y);
            h0 = hn;
            *(float2*)(v0 + XOFF + c0) = hn;
            *(float2*)(g_rnn + ((size_t)r0 * SEQ + s) * 128 + dir * 64 + c0) = hn;
        }
        // gates row1
        {
            float2 z, r, hh, hn;
            z.x = sigm_f(z1.x);  z.y = sigm_f(z1.y);
            r.x = sigm_f(rg1.x); r.y = sigm_f(rg1.y);
            hh.x = tanh_f(hx1.x + r.x * hu1.x);
            hh.y = tanh_f(hx1.y + r.y * hu1.y);
            hn.x = hh.x + z.x * (h1.x - hh.x);
            hn.y = hh.y + z.y * (h1.y - hh.y);
            hn.x = h1.x + m1 * (hn.x - h1.x);
            hn.y = h1.y + m1 * (hn.y - h1.y);
            h1 = hn;
            *(float2*)(v1 + XOFF + c0) = hn;
            *(float2*)(g_rnn + ((size_t)r1 * SEQ + s) * 128 + dir * 64 + c0) = hn;
        }

        xa = xna; xb = xnb; m0 = mn0; m1 = mn1;
    }

    if (dir == 0) {
        *(float2*)(g_hT + r0 * HID + c0) = h0;
        *(float2*)(g_hT + r1 * HID + c0) = h1;
    }
}

// ---------------- K3: attention pooling ------------------------------------
// one block (256 thr) per batch row
__global__ __launch_bounds__(256) void attn_kernel(
    const float* __restrict__ Wk, const float* __restrict__ bk,
    const float* __restrict__ Wq, const float* __restrict__ bq,
    const float* __restrict__ We, const float* __restrict__ be,
    float* __restrict__ out)
{
    __shared__ float Wk_sh[128 * 64];
    __shared__ float q_sh[64];
    __shared__ float e_sh[SEQ];
    __shared__ float red[256];

    const int b = blockIdx.x;
    const int tid = threadIdx.x;
    const int lane = tid & 31, wid = tid >> 5;

    for (int idx = tid; idx < 128 * 64; idx += 256) Wk_sh[idx] = Wk[idx];
    if (tid < 64) {
        float acc = bq[tid];
        #pragma unroll 8
        for (int k = 0; k < HID; ++k) acc += g_hT[b * HID + k] * Wq[k * 64 + tid];
        q_sh[tid] = acc;
    }
    __syncthreads();

    // per-warp constants
    float2 we2 = make_float2(We[2 * lane], We[2 * lane + 1]);
    float  beb = be[0];
    float2 bk2 = make_float2(bk[2 * lane], bk[2 * lane + 1]);
    float  q2a = q_sh[2 * lane], q2b = q_sh[2 * lane + 1];

    // pass A: attention logits
    for (int s = wid; s < SEQ; s += 8) {
        const float* orow = g_rnn + ((size_t)b * SEQ + s) * 128;
        float4 o4 = *(const float4*)(orow + 4 * lane);
        float2 acc = bk2;
        #pragma unroll 8
        for (int sl = 0; sl < 32; ++sl) {
            float fx = __shfl_sync(0xffffffffu, o4.x, sl);
            float fy = __shfl_sync(0xffffffffu, o4.y, sl);
            float fz = __shfl_sync(0xffffffffu, o4.z, sl);
            float fw = __shfl_sync(0xffffffffu, o4.w, sl);
            int kb = sl * 4;
            acc = ffma2f(make_float2(fx, fx), *(const float2*)&Wk_sh[(kb + 0) * 64 + 2 * lane], acc);
            acc = ffma2f(make_float2(fy, fy), *(const float2*)&Wk_sh[(kb + 1) * 64 + 2 * lane], acc);
            acc = ffma2f(make_float2(fz, fz), *(const float2*)&Wk_sh[(kb + 2) * 64 + 2 * lane], acc);
            acc = ffma2f(make_float2(fw, fw), *(const float2*)&Wk_sh[(kb + 3) * 64 + 2 * lane], acc);
        }
        float tx = tanh_f(acc.x + q2a);
        float ty = tanh_f(acc.y + q2b);
        float p = tx * we2.x + ty * we2.y;
        #pragma unroll
        for (int off = 16; off; off >>= 1) p += __shfl_xor_sync(0xffffffffu, p, off);
        if (lane == 0) {
            float m = g_mask[b * SEQ + s];
            e_sh[s] = p + beb + (1.0f - m) * (-1e9f);
        }
    }
    __syncthreads();

    // softmax over S
    red[tid] = (tid < SEQ) ? e_sh[tid] : -3.4e38f;
    __syncthreads();
    for (int o = 128; o; o >>= 1) {
        if (tid < o) red[tid] = fmaxf(red[tid], red[tid + o]);
        __syncthreads();
    }
    float maxv = red[0];
    __syncthreads();
    float wv = (tid < SEQ) ? __expf(e_sh[tid] - maxv) : 0.0f;
    red[tid] = wv;
    __syncthreads();
    for (int o = 128; o; o >>= 1) {
        if (tid < o) red[tid] += red[tid + o];
        __syncthreads();
    }
    float tot = red[0];
    __syncthreads();
    if (tid < SEQ) e_sh[tid] = __fdividef(wv, tot);
    __syncthreads();

    // pass B: weighted sum
    int j = tid & 127, half = tid >> 7;
    float acc = 0.0f;
    const float* orow = g_rnn + ((size_t)b * SEQ) * 128 + j;
    for (int s2 = half * 100; s2 < half * 100 + 100; ++s2)
        acc += e_sh[s2] * orow[(size_t)s2 * 128];
    red[tid] = acc;
    __syncthreads();
    if (tid < 128) out[b * 128 + tid] = red[tid] + red[tid + 128];
}

// ---------------- launch ----------------------------------------------------
extern "C" void kernel_launch(void* const* d_in, const int* in_sizes, int n_in,
                              void* d_out, int out_size)
{
    const int*   inp = (const int*)d_in[0];
    const float* emb = (const float*)d_in[1];
    const float* Wf  = (const float*)d_in[2];
    const float* Uf  = (const float*)d_in[3];
    const float* bf  = (const float*)d_in[4];
    const float* Wb  = (const float*)d_in[5];
    const float* Ub  = (const float*)d_in[6];
    const float* bb  = (const float*)d_in[7];
    const float* Wk  = (const float*)d_in[8];
    const float* bk  = (const float*)d_in[9];
    const float* Wq  = (const float*)d_in[10];
    const float* bq  = (const float*)d_in[11];
    const float* We  = (const float*)d_in[12];
    const float* be  = (const float*)d_in[13];
    float* out = (float*)d_out;

    const int smem = (KV * C3 + 8 * KV) * 4;   // 73600 B
    cudaFuncSetAttribute(gru_kernel, cudaFuncAttributeMaxDynamicSharedMemorySize, smem);

    embed_kernel<<<(BATCH * SEQ) / 8, 256>>>(inp, emb);
    gru_kernel<<<128, 128, smem>>>(Wf, Uf, bf, Wb, Ub, bb);
    attn_kernel<<<BATCH, 256>>>(Wk, bk, Wq, bq, We, be, out);
}

// round 3
// speedup vs baseline: 1.2371x; 1.2371x over previous
#include <cuda_runtime.h>
#include <cuda_bf16.h>

// Problem constants
#define BATCH 512
#define SEQ   200
#define BS    (BATCH*SEQ)   // 102400
#define TT    10
#define EMB   25
#define HID   64
#define C3    192           // 3*HID

// ---------------- scratch (device globals: no allocation allowed) ----------
__device__ float g_x[BS * EMB];                  // mean-pooled embeddings
__device__ float g_mask[BS];                     // step mask as float 0/1
__device__ float g_xp[2ull * BS * C3];           // x projections, both dirs (157MB)
__device__ float g_rnn[(size_t)BS * 128];        // concat(hs_f, hs_b)
__device__ float g_hT[BATCH * HID];              // final forward hidden

#define XPD ((size_t)BS * C3)

// ---------------- helpers --------------------------------------------------
union F2U { float2 f; unsigned long long u; };

static __device__ __forceinline__ float2 ffma2f(float2 a, float2 b, float2 c) {
    F2U A, B, C, D; A.f = a; B.f = b; C.f = c;
    asm("fma.rn.f32x2 %0, %1, %2, %3;" : "=l"(D.u) : "l"(A.u), "l"(B.u), "l"(C.u));
    return D.f;
}

static __device__ __forceinline__ float sigm_f(float x) {
    return __fdividef(1.0f, 1.0f + __expf(-x));
}
static __device__ __forceinline__ float tanh_f(float x) {
    float e = __expf(2.0f * x);
    return 1.0f - __fdividef(2.0f, e + 1.0f);
}

// ---------------- K1: embedding mean + step mask ---------------------------
// one warp per (b, s)
__global__ __launch_bounds__(256) void embed_kernel(
    const int* __restrict__ inp, const float* __restrict__ emb)
{
    int wid = threadIdx.x >> 5, lane = threadIdx.x & 31;
    int g = blockIdx.x * 8 + wid;               // (b,s) index
    if (g >= BS) return;
    int base = g * TT;

    int tk = 0;
    if (lane < TT) tk = inp[base + lane];
    unsigned bal = __ballot_sync(0xffffffffu, (lane < TT) && (tk != 0));
    int cnt = __popc(bal);

    float acc = 0.0f;
    #pragma unroll
    for (int t = 0; t < TT; ++t) {
        int tok = __shfl_sync(0xffffffffu, tk, t);
        if (tok != 0 && lane < EMB) acc += emb[tok * EMB + lane];
    }
    float denom = (float)(cnt > 0 ? cnt : 1);
    if (lane < EMB) g_x[g * EMB + lane] = acc / denom;
    int tok0 = __shfl_sync(0xffffffffu, tk, 0);
    if (lane == 0) g_mask[g] = (tok0 != 0) ? 1.0f : 0.0f;
}

// ---------------- K1b: x projection (both directions) ----------------------
// block = 32 rows, 8 warps x R=4 rows.  xp = x @ W + b0, stored per dir.
__global__ __launch_bounds__(256) void xproj_kernel(
    const float* __restrict__ Wf, const float* __restrict__ bf,
    const float* __restrict__ Wb, const float* __restrict__ bb)
{
    __shared__ float2 Wsh[2][EMB][96];   // [dir][k][colpair]
    __shared__ float2 xsh[32][26];       // duplicated pairs {v,v}

    const int tid = threadIdx.x;
    const int base = blockIdx.x * 32;

    const float2* wf2 = (const float2*)Wf;
    const float2* wb2 = (const float2*)Wb;
    for (int i = tid; i < EMB * 96; i += 256) {
        ((float2*)Wsh)[i] = wf2[i];
        ((float2*)Wsh)[EMB * 96 + i] = wb2[i];
    }
    for (int i = tid; i < 32 * EMB; i += 256) {
        float v = g_x[(size_t)base * EMB + i];
        xsh[i / EMB][i % EMB] = make_float2(v, v);
    }
    __syncthreads();

    const int w = tid >> 5, lane = tid & 31, c0 = 2 * lane;

    float2 bf0 = *(const float2*)&bf[c0];
    float2 bf1 = *(const float2*)&bf[64 + c0];
    float2 bf2v = *(const float2*)&bf[128 + c0];
    float2 bb0 = *(const float2*)&bb[c0];
    float2 bb1 = *(const float2*)&bb[64 + c0];
    float2 bb2v = *(const float2*)&bb[128 + c0];

    float2 af[4][3], ab[4][3];
    #pragma unroll
    for (int r = 0; r < 4; ++r) {
        af[r][0] = bf0; af[r][1] = bf1; af[r][2] = bf2v;
        ab[r][0] = bb0; ab[r][1] = bb1; ab[r][2] = bb2v;
    }

    #pragma unroll 5
    for (int k = 0; k < EMB; ++k) {
        float2 wfz = Wsh[0][k][lane], wfr = Wsh[0][k][32 + lane], wfh = Wsh[0][k][64 + lane];
        float2 wbz = Wsh[1][k][lane], wbr = Wsh[1][k][32 + lane], wbh = Wsh[1][k][64 + lane];
        #pragma unroll
        for (int r = 0; r < 4; ++r) {
            float2 xv = xsh[w * 4 + r][k];
            af[r][0] = ffma2f(xv, wfz, af[r][0]);
            af[r][1] = ffma2f(xv, wfr, af[r][1]);
            af[r][2] = ffma2f(xv, wfh, af[r][2]);
            ab[r][0] = ffma2f(xv, wbz, ab[r][0]);
            ab[r][1] = ffma2f(xv, wbr, ab[r][1]);
            ab[r][2] = ffma2f(xv, wbh, ab[r][2]);
        }
    }

    #pragma unroll
    for (int r = 0; r < 4; ++r) {
        size_t g = (size_t)base + w * 4 + r;
        float* of = g_xp + g * C3;
        *(float2*)&of[c0]       = af[r][0];
        *(float2*)&of[64 + c0]  = af[r][1];
        *(float2*)&of[128 + c0] = af[r][2];
        float* ob = g_xp + XPD + g * C3;
        *(float2*)&ob[c0]       = ab[r][0];
        *(float2*)&ob[64 + c0]  = ab[r][1];
        *(float2*)&ob[128 + c0] = ab[r][2];
    }
}

// ---------------- K2: bidirectional GRU scan (register-resident U) ---------
// 128 blocks x 256 threads. Block = (dir, 8 batch rows). 8 warps:
//   FMA role: warp w -> rows ((w&1)*4 .. +3), k-quarter (w>>2... w>>1)*16
//   Gate role: warp w -> local row w
__global__ __launch_bounds__(256, 1) void gru_kernel(
    const float* __restrict__ Uf, const float* __restrict__ bf,
    const float* __restrict__ Ub, const float* __restrict__ bb)
{
    __shared__ float2 h2[8][64];        // duplicated pairs {h,h}
    __shared__ float2 part[4][8][96];   // [kq][row][colpair]

    const int tid = threadIdx.x;
    const int w = tid >> 5, lane = tid & 31, c0 = 2 * lane;
    const int dir = blockIdx.x >> 6;
    const int rowbase = (blockIdx.x & 63) * 8;
    const float* Um = dir ? Ub : Uf;
    const float* bm = dir ? bb : bf;

    const int rg = (w & 1) * 4;         // FMA row group
    const int kq = w >> 1;              // k quarter (0..3)

    // load U slice to registers: 16 k-rows x (3 gates x 2 cols)
    float2 Uz[16], Ur[16], Uh[16];
    #pragma unroll
    for (int k = 0; k < 16; ++k) {
        const float* up = Um + (kq * 16 + k) * C3;
        Uz[k] = *(const float2*)&up[c0];
        Ur[k] = *(const float2*)&up[64 + c0];
        Uh[k] = *(const float2*)&up[128 + c0];
    }

    // gate-phase constants for this warp's row
    const int grow = rowbase + w;
    float2 b1z = *(const float2*)&bm[192 + c0];
    float2 b1r = *(const float2*)&bm[256 + c0];
    float2 b1h = *(const float2*)&bm[320 + c0];
    const float* xpbase = g_xp + (size_t)dir * XPD + (size_t)grow * SEQ * C3;

    float2 hprev = make_float2(0.f, 0.f);
    h2[w][lane] = make_float2(0.f, 0.f);
    h2[w][32 + lane] = make_float2(0.f, 0.f);
    __syncthreads();

    // prefetch xp + mask for t=0
    int s0 = dir ? (SEQ - 1) : 0;
    const float* xp0 = xpbase + (size_t)s0 * C3;
    float2 xz = *(const float2*)&xp0[c0];
    float2 xr = *(const float2*)&xp0[64 + c0];
    float2 xh = *(const float2*)&xp0[128 + c0];
    float mk = g_mask[grow * SEQ + s0];

    for (int t = 0; t < SEQ; ++t) {
        int s = dir ? (SEQ - 1 - t) : t;

        // ---- FMA phase: partial h @ U for 4 rows over 16 k ----
        float2 az[4], ar[4], ah[4];
        #pragma unroll
        for (int r = 0; r < 4; ++r) {
            az[r] = make_float2(0.f, 0.f);
            ar[r] = make_float2(0.f, 0.f);
            ah[r] = make_float2(0.f, 0.f);
        }
        #pragma unroll
        for (int k = 0; k < 16; ++k) {
            float2 h0 = h2[rg + 0][kq * 16 + k];
            float2 h1 = h2[rg + 1][kq * 16 + k];
            float2 hv2 = h2[rg + 2][kq * 16 + k];
            float2 h3 = h2[rg + 3][kq * 16 + k];
            az[0] = ffma2f(h0, Uz[k], az[0]); ar[0] = ffma2f(h0, Ur[k], ar[0]); ah[0] = ffma2f(h0, Uh[k], ah[0]);
            az[1] = ffma2f(h1, Uz[k], az[1]); ar[1] = ffma2f(h1, Ur[k], ar[1]); ah[1] = ffma2f(h1, Uh[k], ah[1]);
            az[2] = ffma2f(hv2, Uz[k], az[2]); ar[2] = ffma2f(hv2, Ur[k], ar[2]); ah[2] = ffma2f(hv2, Uh[k], ah[2]);
            az[3] = ffma2f(h3, Uz[k], az[3]); ar[3] = ffma2f(h3, Ur[k], ar[3]); ah[3] = ffma2f(h3, Uh[k], ah[3]);
        }
        #pragma unroll
        for (int r = 0; r < 4; ++r) {
            part[kq][rg + r][lane]      = az[r];
            part[kq][rg + r][32 + lane] = ar[r];
            part[kq][rg + r][64 + lane] = ah[r];
        }
        __syncthreads();

        // ---- gate phase: warp w handles local row w ----
        float2 pz, pr, ph;
        {
            float2 a0 = part[0][w][lane], a1 = part[1][w][lane],
                   a2 = part[2][w][lane], a3 = part[3][w][lane];
            pz = make_float2(a0.x + a1.x + a2.x + a3.x, a0.y + a1.y + a2.y + a3.y);
            a0 = part[0][w][32 + lane]; a1 = part[1][w][32 + lane];
            a2 = part[2][w][32 + lane]; a3 = part[3][w][32 + lane];
            pr = make_float2(a0.x + a1.x + a2.x + a3.x, a0.y + a1.y + a2.y + a3.y);
            a0 = part[0][w][64 + lane]; a1 = part[1][w][64 + lane];
            a2 = part[2][w][64 + lane]; a3 = part[3][w][64 + lane];
            ph = make_float2(a0.x + a1.x + a2.x + a3.x, a0.y + a1.y + a2.y + a3.y);
        }
        float zx = sigm_f(xz.x + pz.x + b1z.x);
        float zy = sigm_f(xz.y + pz.y + b1z.y);
        float rx = sigm_f(xr.x + pr.x + b1r.x);
        float ry = sigm_f(xr.y + pr.y + b1r.y);
        float hhx = tanh_f(xh.x + rx * (ph.x + b1h.x));
        float hhy = tanh_f(xh.y + ry * (ph.y + b1h.y));
        float hnx = hhx + zx * (hprev.x - hhx);
        float hny = hhy + zy * (hprev.y - hhy);
        hnx = hprev.x + mk * (hnx - hprev.x);
        hny = hprev.y + mk * (hny - hprev.y);
        hprev = make_float2(hnx, hny);

        // write duplicated h pair + output row
        *(float4*)&h2[w][c0] = make_float4(hnx, hnx, hny, hny);
        *(float2*)&g_rnn[((size_t)grow * SEQ + s) * 128 + dir * 64 + c0] = hprev;

        // prefetch next step's xp + mask (covered by barrier + next FMA phase)
        if (t < SEQ - 1) {
            int sn = dir ? (SEQ - 2 - t) : (t + 1);
            const float* xpn = xpbase + (size_t)sn * C3;
            xz = *(const float2*)&xpn[c0];
            xr = *(const float2*)&xpn[64 + c0];
            xh = *(const float2*)&xpn[128 + c0];
            mk = g_mask[grow * SEQ + sn];
        }
        __syncthreads();
    }

    if (dir == 0) *(float2*)&g_hT[grow * HID + c0] = hprev;
}

// ---------------- K3: attention pooling ------------------------------------
// one block (256 thr) per batch row; dynamic smem
__global__ __launch_bounds__(256) void attn_kernel(
    const float* __restrict__ Wk, const float* __restrict__ bk,
    const float* __restrict__ Wq, const float* __restrict__ bq,
    const float* __restrict__ We, const float* __restrict__ be,
    float* __restrict__ out)
{
    extern __shared__ float dsm[];
    float4* Wk4 = (float4*)dsm;                 // [64][32]: paired k rows (8192 floats)
    float2* ost = (float2*)(dsm + 8192);        // [8][5][128] dup pairs (10240 floats)
    float* q_sh = dsm + 8192 + 10240;           // 64
    float* e_sh = q_sh + 64;                    // SEQ (200)
    float* red  = e_sh + SEQ;                   // 256

    const int b = blockIdx.x;
    const int tid = threadIdx.x;
    const int lane = tid & 31, wid = tid >> 5;

    // pack Wk: Wk4[k2*32+j] = {Wk[2k2][2j], Wk[2k2][2j+1], Wk[2k2+1][2j], Wk[2k2+1][2j+1]}
    for (int i = tid; i < 64 * 32; i += 256) {
        int k2 = i >> 5, j = i & 31;
        float2 a = *(const float2*)&Wk[(2 * k2) * 64 + 2 * j];
        float2 c = *(const float2*)&Wk[(2 * k2 + 1) * 64 + 2 * j];
        Wk4[i] = make_float4(a.x, a.y, c.x, c.y);
    }
    if (tid < 64) {
        float acc = bq[tid];
        #pragma unroll 8
        for (int k = 0; k < HID; ++k) acc += g_hT[b * HID + k] * Wq[k * 64 + tid];
        q_sh[tid] = acc;
    }
    __syncthreads();

    float2 we2 = make_float2(We[2 * lane], We[2 * lane + 1]);
    float  beb = be[0];
    float2 bk2 = make_float2(bk[2 * lane], bk[2 * lane + 1]);
    float  q2a = q_sh[2 * lane], q2b = q_sh[2 * lane + 1];

    // pass A: logits — warp owns steps [wid*25, wid*25+25), 5 iters of 5 staged steps
    for (int it = 0; it < 5; ++it) {
        int sb = wid * 25 + it * 5;
        // stage 5 rows as duplicated pairs
        #pragma unroll
        for (int r = 0; r < 5; ++r) {
            float4 o4 = *(const float4*)&g_rnn[((size_t)b * SEQ + sb + r) * 128 + 4 * lane];
            float2* dst = ost + ((wid * 5 + r) * 128 + 4 * lane);
            dst[0] = make_float2(o4.x, o4.x);
            dst[1] = make_float2(o4.y, o4.y);
            dst[2] = make_float2(o4.z, o4.z);
            dst[3] = make_float2(o4.w, o4.w);
        }
        __syncwarp();

        float2 acc[5];
        #pragma unroll
        for (int r = 0; r < 5; ++r) acc[r] = bk2;

        #pragma unroll 8
        for (int k2 = 0; k2 < 64; ++k2) {
            float4 wk = Wk4[k2 * 32 + lane];
            float2 wkA = make_float2(wk.x, wk.y);
            float2 wkB = make_float2(wk.z, wk.w);
            #pragma unroll
            for (int r = 0; r < 5; ++r) {
                float4 ov = *(const float4*)&ost[(wid * 5 + r) * 128 + 2 * k2];
                acc[r] = ffma2f(make_float2(ov.x, ov.y), wkA, acc[r]);
                acc[r] = ffma2f(make_float2(ov.z, ov.w), wkB, acc[r]);
            }
        }

        #pragma unroll
        for (int r = 0; r < 5; ++r) {
            float ex = tanh_f(acc[r].x + q2a) * we2.x + tanh_f(acc[r].y + q2b) * we2.y;
            #pragma unroll
            for (int off = 16; off; off >>= 1) ex += __shfl_xor_sync(0xffffffffu, ex, off);
            if (lane == 0) {
                float m = g_mask[b * SEQ + sb + r];
                e_sh[sb + r] = ex + beb + (1.0f - m) * (-1e9f);
            }
        }
        __syncwarp();
    }
    __syncthreads();

    // softmax over S
    red[tid] = (tid < SEQ) ? e_sh[tid] : -3.4e38f;
    __syncthreads();
    for (int o = 128; o; o >>= 1) {
        if (tid < o) red[tid] = fmaxf(red[tid], red[tid + o]);
        __syncthreads();
    }
    float maxv = red[0];
    __syncthreads();
    float wv = (tid < SEQ) ? __expf(e_sh[tid] - maxv) : 0.0f;
    red[tid] = wv;
    __syncthreads();
    for (int o = 128; o; o >>= 1) {
        if (tid < o) red[tid] += red[tid + o];
        __syncthreads();
    }
    float tot = red[0];
    __syncthreads();
    if (tid < SEQ) e_sh[tid] = __fdividef(wv, tot);
    __syncthreads();

    // pass B: weighted sum
    int j = tid & 127, half = tid >> 7;
    float acc = 0.0f;
    const float* orow = g_rnn + ((size_t)b * SEQ) * 128 + j;
    for (int s2 = half * 100; s2 < half * 100 + 100; ++s2)
        acc += e_sh[s2] * orow[(size_t)s2 * 128];
    red[tid] = acc;
    __syncthreads();
    if (tid < 128) out[b * 128 + tid] = red[tid] + red[tid + 128];
}

// ---------------- launch ----------------------------------------------------
extern "C" void kernel_launch(void* const* d_in, const int* in_sizes, int n_in,
                              void* d_out, int out_size)
{
    const int*   inp = (const int*)d_in[0];
    const float* emb = (const float*)d_in[1];
    const float* Wf  = (const float*)d_in[2];
    const float* Uf  = (const float*)d_in[3];
    const float* bf  = (const float*)d_in[4];
    const float* Wb  = (const float*)d_in[5];
    const float* Ub  = (const float*)d_in[6];
    const float* bb  = (const float*)d_in[7];
    const float* Wk  = (const float*)d_in[8];
    const float* bk  = (const float*)d_in[9];
    const float* Wq  = (const float*)d_in[10];
    const float* bq  = (const float*)d_in[11];
    const float* We  = (const float*)d_in[12];
    const float* be  = (const float*)d_in[13];
    float* out = (float*)d_out;

    const int attn_smem = (8192 + 10240 + 64 + SEQ + 256) * 4;
    cudaFuncSetAttribute(attn_kernel, cudaFuncAttributeMaxDynamicSharedMemorySize, attn_smem);

    embed_kernel<<<BS / 8, 256>>>(inp, emb);
    xproj_kernel<<<BS / 32, 256>>>(Wf, bf, Wb, bb);
    gru_kernel<<<128, 256>>>(Uf, bf, Ub, bb);
    attn_kernel<<<BATCH, 256, attn_smem>>>(Wk, bk, Wq, bq, We, be, out);
}